// round 16
// baseline (speedup 1.0000x reference)
#include <cuda_runtime.h>
#include <cuda_bf16.h>
#include <cstdint>

// C = triu(triu(A) @ triu(B)), N = 4096, fp32.
// sm_103a path: A,B pre-split into masked bf16 hi/lo (B transposed K-major);
// main kernel: 2-CTA cluster (cta_group::2) tiles of 256x128 — M split 128
// rows/CTA, N split 64 cols/CTA. Warp-specialized: 8 producer warps (cp.async)
// + 1 MMA warp (leader CTA only). Per-stage full (leader, count 16, cluster
// arrivals) / empty (per CTA, multicast cg2 commit). 4 stages, KC=32 (SW64),
// 3 bf16 MMAs per K16 (h*h + h*l + l*h), fp32 accum in TMEM (rank-row split).
// Longest-k-first tile order. Fallback (generic PTX): SIMT fp32, same mapping.

constexpr int NMAT = 4096;
constexpr int BM = 256;        // pair tile rows (128 per CTA)
constexpr int BN = 128;        // pair tile cols (64 per CTA in SMEM)
constexpr int KC = 32;         // k-chunk (32 bf16 = 64B rows, SW64 native)
constexpr int THREADS = 288;   // 8 producer warps + 1 MMA warp
constexpr int PROD = 256;
constexpr int STAGES = 4;
constexpr int NCOMPUTE = 272;  // tiles with 2*br2 <= bc  (16 x 32 bands)
constexpr int ENTRIES = 512;   // 272 compute + 240 zero tiles

// Scratch: masked splits. gA0/gA1: A [r][k]. gB0/gB1: B^T [c][k]. All K-major.
__device__ __align__(1024) __nv_bfloat16 gA0[(size_t)NMAT * NMAT];
__device__ __align__(1024) __nv_bfloat16 gA1[(size_t)NMAT * NMAT];
__device__ __align__(1024) __nv_bfloat16 gB0[(size_t)NMAT * NMAT];
__device__ __align__(1024) __nv_bfloat16 gB1[(size_t)NMAT * NMAT];

// ---------------------------------------------------------------- helpers
__device__ __forceinline__ uint32_t smem_u32(const void* p) {
    uint32_t a;
    asm("{ .reg .u64 t; cvta.to.shared.u64 t, %1; cvt.u32.u64 %0, t; }"
        : "=r"(a) : "l"(p));
    return a;
}

#if defined(__CUDA_ARCH_FEAT_SM103_ALL) || !defined(__CUDA_ARCH__)
__device__ __forceinline__ void mma_f16_ss_cg2(uint32_t d, uint64_t ad,
                                               uint64_t bd, uint32_t idesc,
                                               uint32_t en) {
    asm volatile(
        "{\n\t.reg .pred p;\n\tsetp.ne.u32 p, %6, 0;\n\t"
        "tcgen05.mma.cta_group::2.kind::f16 [%0], %1, %2, %3, "
        "{%4,%4,%4,%4,%4,%4,%4,%4}, p;\n\t}"
        :: "r"(d), "l"(ad), "l"(bd), "r"(idesc),
           "r"(0u), "r"(0u), "r"(en) : "memory");
}
__device__ __forceinline__ void cp_async16(uint32_t dst, const void* src) {
    asm volatile("cp.async.cg.shared.global [%0], [%1], 16;"
                 :: "r"(dst), "l"(src) : "memory");
}
#define CP_COMMIT()      asm volatile("cp.async.commit_group;" ::: "memory")
#define CP_WAIT0()       asm volatile("cp.async.wait_group 0;" ::: "memory")
#define CP_WAIT1()       asm volatile("cp.async.wait_group 1;" ::: "memory")
#define TC_ALLOC_CG2(sl, n)  asm volatile("tcgen05.alloc.cta_group::2.sync.aligned.shared::cta.b32 [%0], %1;" :: "r"(sl), "r"((uint32_t)(n)) : "memory")
#define TC_RELINQ_CG2()      asm volatile("tcgen05.relinquish_alloc_permit.cta_group::2.sync.aligned;")
#define TC_DEALLOC_CG2(t, n) asm volatile("tcgen05.dealloc.cta_group::2.sync.aligned.b32 %0, %1;" :: "r"(t), "r"((uint32_t)(n)))
#define TC_COMMIT_MC2(mb, mask) asm volatile("tcgen05.commit.cta_group::2.mbarrier::arrive::one.shared::cluster.multicast::cluster.b64 [%0], %1;" :: "r"(mb), "h"((uint16_t)(mask)) : "memory")
#define TC_FENCE_AFTER() asm volatile("tcgen05.fence::after_thread_sync;" ::: "memory")
#define TC_FENCE_BEFORE() asm volatile("tcgen05.fence::before_thread_sync;" ::: "memory")
#define TC_WAIT_LD()     asm volatile("tcgen05.wait::ld.sync.aligned;" ::: "memory")
#define FENCE_ASYNC()    asm volatile("fence.proxy.async.shared::cta;" ::: "memory")
#define MBAR_INIT(mb, c) asm volatile("mbarrier.init.shared.b64 [%0], %1;" :: "r"(mb), "r"((uint32_t)(c)) : "memory")
// Arrive on the LEADER CTA's (rank 0) mbarrier at the same SMEM offset.
#define MBAR_ARRIVE_RANK0(mb) \
    asm volatile("{\n\t.reg .b32 ra;\n\tmapa.shared::cluster.u32 ra, %0, 0;\n\t" \
                 "mbarrier.arrive.shared::cluster.b64 _, [ra];\n\t}" \
                 :: "r"(mb) : "memory")
#define CLUSTER_SYNC() do { \
    asm volatile("barrier.cluster.arrive.aligned;" ::: "memory"); \
    asm volatile("barrier.cluster.wait.aligned;" ::: "memory"); } while (0)

#define MBAR_WAIT_PARITY(mb, ph) do {                                           \
    uint32_t _m = (mb), _p = (ph), _d;                                          \
    asm volatile("{\n\t.reg .pred p;\n\t"                                       \
        "mbarrier.try_wait.parity.acquire.cta.shared::cta.b64 p, [%1], %2;\n\t" \
        "selp.b32 %0, 1, 0, p;\n\t}" : "=r"(_d) : "r"(_m), "r"(_p) : "memory"); \
    if (!_d) {                                                                  \
        asm volatile("{\n\t.reg .pred P1;\n\t"                                  \
        "WL_%=:\n\t"                                                            \
        "mbarrier.try_wait.parity.acquire.cta.shared::cta.b64 P1, [%0], %1, 0x989680;\n\t" \
        "@P1 bra.uni WD_%=;\n\t"                                                \
        "bra.uni WL_%=;\n\t"                                                    \
        "WD_%=:\n\t}" :: "r"(_m), "r"(_p) : "memory");                          \
    }                                                                           \
} while (0)

// Cluster-scope acquire (leader consuming cross-CTA release-arrivals).
#define MBAR_WAIT_PARITY_CL(mb, ph) do {                                        \
    uint32_t _m = (mb), _p = (ph), _d;                                          \
    asm volatile("{\n\t.reg .pred p;\n\t"                                       \
        "mbarrier.try_wait.parity.acquire.cluster.shared::cta.b64 p, [%1], %2;\n\t" \
        "selp.b32 %0, 1, 0, p;\n\t}" : "=r"(_d) : "r"(_m), "r"(_p) : "memory"); \
    if (!_d) {                                                                  \
        asm volatile("{\n\t.reg .pred P1;\n\t"                                  \
        "WL_%=:\n\t"                                                            \
        "mbarrier.try_wait.parity.acquire.cluster.shared::cta.b64 P1, [%0], %1, 0x989680;\n\t" \
        "@P1 bra.uni WD_%=;\n\t"                                                \
        "bra.uni WL_%=;\n\t"                                                    \
        "WD_%=:\n\t}" :: "r"(_m), "r"(_p) : "memory");                          \
    }                                                                           \
} while (0)

#define LDTM_X32(r, a)                                                          \
    asm volatile("tcgen05.ld.sync.aligned.32x32b.x32.b32 "                      \
        "{%0, %1, %2, %3, %4, %5, %6, %7, %8, %9, %10, %11, %12, %13, %14, %15,"\
        " %16, %17, %18, %19, %20, %21, %22, %23, %24, %25, %26, %27, %28, %29, %30, %31}, [%32];" \
        : "=r"((r)[0]), "=r"((r)[1]), "=r"((r)[2]), "=r"((r)[3]),               \
          "=r"((r)[4]), "=r"((r)[5]), "=r"((r)[6]), "=r"((r)[7]),               \
          "=r"((r)[8]), "=r"((r)[9]), "=r"((r)[10]), "=r"((r)[11]),             \
          "=r"((r)[12]), "=r"((r)[13]), "=r"((r)[14]), "=r"((r)[15]),           \
          "=r"((r)[16]), "=r"((r)[17]), "=r"((r)[18]), "=r"((r)[19]),           \
          "=r"((r)[20]), "=r"((r)[21]), "=r"((r)[22]), "=r"((r)[23]),           \
          "=r"((r)[24]), "=r"((r)[25]), "=r"((r)[26]), "=r"((r)[27]),           \
          "=r"((r)[28]), "=r"((r)[29]), "=r"((r)[30]), "=r"((r)[31])            \
        : "r"(a))
#endif  // tcgen05 helpers

// SW64 smem descriptor (K-major, 64B rows): layout=SW64(4), ver=1, SBO=32, LBO=1
constexpr uint64_t DESC_BASE_SW64 =
    (uint64_t(4) << 61) | (uint64_t(1) << 46) | (uint64_t(32) << 32) | (uint64_t(1) << 16);
__device__ __forceinline__ uint64_t mk_desc64(uint32_t a) {
    return DESC_BASE_SW64 | ((uint64_t)(a >> 4) & 0x3FFF);
}

__device__ __forceinline__ uint32_t pack_bf16x2(float a, float b) {
    __nv_bfloat162 h = __halves2bfloat162(__float2bfloat16(a), __float2bfloat16(b));
    return *reinterpret_cast<uint32_t*>(&h);
}

// ---------------------------------------------------------------- pre-pass
// z=0: gA0/gA1[r][k] = hi/lo bf16 of (k>=r ? A[r][k] : 0)   (row-major copy)
// z=1: gB0/gB1[c][k] = hi/lo bf16 of (k<=c ? B[k][c] : 0)   (transpose)
// Skip bounds match 256-row / 128-col main-kernel bands.
__global__ __launch_bounds__(256)
void split_ab_kernel(const float* __restrict__ A, const float* __restrict__ B) {
    const int tid = threadIdx.x;

    if (blockIdx.z == 0) {
        const int rb = blockIdx.y * 64, kb = blockIdx.x * 64;
        if (kb < (rb & ~255)) return;            // k < row0 of 256-band: unread
        const int r = rb + (tid >> 2);
        const int k0 = kb + (tid & 3) * 16;
        uint32_t hw[8], lw[8];
        if (kb + 63 < rb) {                       // read, but fully masked
            #pragma unroll
            for (int i = 0; i < 8; ++i) { hw[i] = 0u; lw[i] = 0u; }
        } else {
            #pragma unroll
            for (int q = 0; q < 4; ++q) {
                float4 v = *reinterpret_cast<const float4*>(
                    A + (size_t)r * NMAT + k0 + q * 4);
                const int kg = k0 + q * 4;
                float x0 = (kg + 0 >= r) ? v.x : 0.f;
                float x1 = (kg + 1 >= r) ? v.y : 0.f;
                float x2 = (kg + 2 >= r) ? v.z : 0.f;
                float x3 = (kg + 3 >= r) ? v.w : 0.f;
                float h0 = __bfloat162float(__float2bfloat16(x0));
                float h1 = __bfloat162float(__float2bfloat16(x1));
                float h2 = __bfloat162float(__float2bfloat16(x2));
                float h3 = __bfloat162float(__float2bfloat16(x3));
                hw[2 * q + 0] = pack_bf16x2(x0, x1);
                hw[2 * q + 1] = pack_bf16x2(x2, x3);
                lw[2 * q + 0] = pack_bf16x2(x0 - h0, x1 - h1);
                lw[2 * q + 1] = pack_bf16x2(x2 - h2, x3 - h3);
            }
        }
        uint4* p0 = reinterpret_cast<uint4*>(gA0 + (size_t)r * NMAT + k0);
        uint4* p1 = reinterpret_cast<uint4*>(gA1 + (size_t)r * NMAT + k0);
        p0[0] = make_uint4(hw[0], hw[1], hw[2], hw[3]);
        p0[1] = make_uint4(hw[4], hw[5], hw[6], hw[7]);
        p1[0] = make_uint4(lw[0], lw[1], lw[2], lw[3]);
        p1[1] = make_uint4(lw[4], lw[5], lw[6], lw[7]);
        return;
    }

    // ---- B branch: transpose + mask + split, 64x64 tile staged in smem ----
    const int kb = blockIdx.y * 64, cb = blockIdx.x * 64;
    if (kb >= (cb & ~127) + 128) return;          // k > col0+127: unread
    if (kb > cb + 63) {                           // read, but fully masked
        const uint4 z = make_uint4(0, 0, 0, 0);
        int u = tid * 2;
        int c = u >> 3, s = u & 7;
        uint4* p0 = reinterpret_cast<uint4*>(gB0 + (size_t)(cb + c) * NMAT + kb + s * 8);
        uint4* p1 = reinterpret_cast<uint4*>(gB1 + (size_t)(cb + c) * NMAT + kb + s * 8);
        p0[0] = z; p0[1] = z;
        p1[0] = z; p1[1] = z;
        return;
    }

    __shared__ float s[64][65];
    #pragma unroll
    for (int i = 0; i < 4; ++i) {
        int idx = tid + i * 256;
        int k = idx >> 4, cq = (idx & 15) * 4;
        float4 v = *reinterpret_cast<const float4*>(B + (size_t)(kb + k) * NMAT + cb + cq);
        int kg = kb + k;
        s[k][cq + 0] = (kg <= cb + cq + 0) ? v.x : 0.f;
        s[k][cq + 1] = (kg <= cb + cq + 1) ? v.y : 0.f;
        s[k][cq + 2] = (kg <= cb + cq + 2) ? v.z : 0.f;
        s[k][cq + 3] = (kg <= cb + cq + 3) ? v.w : 0.f;
    }
    __syncthreads();

    const int c = tid >> 2;
    const int ks = (tid & 3) * 16;
    float f[16];
    #pragma unroll
    for (int j = 0; j < 16; ++j) f[j] = s[ks + j][c];
    uint32_t h[8], l[8];
    #pragma unroll
    for (int j = 0; j < 8; ++j) {
        float x0 = f[2 * j], x1 = f[2 * j + 1];
        float h0 = __bfloat162float(__float2bfloat16(x0));
        float h1 = __bfloat162float(__float2bfloat16(x1));
        h[j] = pack_bf16x2(x0, x1);
        l[j] = pack_bf16x2(x0 - h0, x1 - h1);
    }
    uint4* p0 = reinterpret_cast<uint4*>(gB0 + (size_t)(cb + c) * NMAT + kb + ks);
    uint4* p1 = reinterpret_cast<uint4*>(gB1 + (size_t)(cb + c) * NMAT + kb + ks);
    p0[0] = make_uint4(h[0], h[1], h[2], h[3]);
    p0[1] = make_uint4(h[4], h[5], h[6], h[7]);
    p1[0] = make_uint4(l[0], l[1], l[2], l[3]);
    p1[1] = make_uint4(l[4], l[5], l[6], l[7]);
}

// ---------------------------------------------------------------- main GEMM
// smem per CTA: ctrl @ +0 (tmemptr @0, full[s] @8+8s, empty[s] @40+8s,
// done @72); STAGES x 24KB buffers @ +1024.
// Per stage: A0 @0 (128x64B=8KB), A1 @8192, B0 @16384 (4KB), B1 @20480.
constexpr int OFF_A0 = 0;
constexpr int OFF_A1 = 8192;
constexpr int OFF_B0 = 16384;
constexpr int OFF_B1 = 20480;
constexpr int STAGE_SZ = 24576;
constexpr int SMEM_NEED = 1024 + STAGES * STAGE_SZ + 1024;

#if defined(__CUDA_ARCH_FEAT_SM103_ALL) || !defined(__CUDA_ARCH__)
// Per-CTA chunk: A = this rank's 128 rows (hi+lo), B = this rank's 64 cols.
__device__ __forceinline__ void issue_chunk(uint32_t bb, int arow0, int bcol0,
                                            int kt, int tid) {
    #pragma unroll
    for (int j = 0; j < 2; ++j) {
        int idx = tid + j * PROD;              // A: 512 segs each
        int m = idx >> 2, seg = idx & 3;
        uint32_t off = m * 64 + seg * 16;
        off ^= (off >> 3) & 0x30;              // SW64
        const __nv_bfloat16* s0 = gA0 + (size_t)(arow0 + m) * NMAT + kt + seg * 8;
        const __nv_bfloat16* s1 = gA1 + (size_t)(arow0 + m) * NMAT + kt + seg * 8;
        cp_async16(bb + OFF_A0 + off, s0);
        cp_async16(bb + OFF_A1 + off, s1);
    }
    {
        int idx = tid;                         // B: 256 segs each
        int crow = idx >> 2, seg = idx & 3;
        uint32_t off = crow * 64 + seg * 16;
        off ^= (off >> 3) & 0x30;              // SW64
        const __nv_bfloat16* s0 = gB0 + (size_t)(bcol0 + crow) * NMAT + kt + seg * 8;
        const __nv_bfloat16* s1 = gB1 + (size_t)(bcol0 + crow) * NMAT + kt + seg * 8;
        cp_async16(bb + OFF_B0 + off, s0);
        cp_async16(bb + OFF_B1 + off, s1);
    }
}
#endif

__global__ __launch_bounds__(THREADS, 1)
void trimm_tc_kernel(const float* __restrict__ A,
                     const float* __restrict__ B,
                     float* __restrict__ C) {
    const int bid = blockIdx.x;
    const int tile = bid >> 1;
    const int rank = bid & 1;                  // cluster_ctarank (cluster x=2)
    const int tid = threadIdx.x;

    // ---- longest-k-first schedule decode (256x128 tiles, 16x32 bands) ----
    int br2, bc;
    bool zero_tile = (tile >= NCOMPUTE);
    if (zero_tile) {
        int z = tile - NCOMPUTE;
        int b2 = 1;
        while (z >= 2 * b2) { z -= 2 * b2; ++b2; }
        br2 = b2; bc = z;
    } else {
        int rem = tile, d = 31;
        for (;; --d) {
            int cnt = ((31 - d) >> 1) + 1;     // 1..16
            if (rem < cnt) break;
            rem -= cnt;
        }
        br2 = rem; bc = d + 2 * rem;
    }
    const int row0 = br2 * BM, col0 = bc * BN;

    if (zero_tile) {
        // each CTA zeros its 128-row half of the 256x128 tile
        const float4 z4 = make_float4(0.f, 0.f, 0.f, 0.f);
        float4* out = reinterpret_cast<float4*>(
            C + (size_t)(row0 + rank * 128) * NMAT + col0);
        for (int idx = tid; idx < 128 * BN / 4; idx += THREADS)
            out[(size_t)(idx >> 5) * (NMAT / 4) + (idx & 31)] = z4;
        return;
    }

    const int nch = (col0 + BN - row0) / KC;     // 4..128, divisible by 4

#if defined(__CUDA_ARCH__) && !defined(__CUDA_ARCH_FEAT_SM103_ALL)
    // -------- arch-generic fallback: SIMT fp32, this rank's 128-row half ----
    constexpr int BK = 8, TM = 8, TN = 8;
    __shared__ float As[BK][128 + 4];
    __shared__ float Bs[BK][128];

    const bool act = (tid < 256);
    const int ty = tid >> 4, tx = tid & 15;
    const int a_row = tid >> 1, a_k = (tid & 1) * 4;
    const int b_k = (tid >> 5) & 7, b_col = (tid & 31) * 4;
    const int row0h = row0 + rank * 128;

    if (row0h > col0 + 127) {   // this half entirely below diagonal
        const float4 z4 = make_float4(0.f, 0.f, 0.f, 0.f);
        float4* out = reinterpret_cast<float4*>(C + (size_t)row0h * NMAT + col0);
        for (int idx = tid; idx < 128 * BN / 4; idx += THREADS)
            out[(size_t)(idx >> 5) * (NMAT / 4) + (idx & 31)] = z4;
        return;
    }
    float acc[TM][TN];
    #pragma unroll
    for (int i = 0; i < TM; ++i)
        #pragma unroll
        for (int j = 0; j < TN; ++j) acc[i][j] = 0.f;
    const int arow_g = row0h + (act ? a_row : 0);
    const int cg = col0 + b_col;
    for (int kt = row0h; kt < col0 + 128; kt += BK) {
        if (act) {
            const float4 av = *reinterpret_cast<const float4*>(
                A + (size_t)arow_g * NMAT + (kt + a_k));
            const int kg = kt + a_k;
            As[a_k + 0][a_row] = (kg + 0 >= arow_g) ? av.x : 0.f;
            As[a_k + 1][a_row] = (kg + 1 >= arow_g) ? av.y : 0.f;
            As[a_k + 2][a_row] = (kg + 2 >= arow_g) ? av.z : 0.f;
            As[a_k + 3][a_row] = (kg + 3 >= arow_g) ? av.w : 0.f;
            const int bkg = kt + b_k;
            float4 bv = *reinterpret_cast<const float4*>(B + (size_t)bkg * NMAT + cg);
            bv.x = (bkg <= cg + 0) ? bv.x : 0.f;
            bv.y = (bkg <= cg + 1) ? bv.y : 0.f;
            bv.z = (bkg <= cg + 2) ? bv.z : 0.f;
            bv.w = (bkg <= cg + 3) ? bv.w : 0.f;
            *reinterpret_cast<float4*>(&Bs[b_k][b_col]) = bv;
        }
        __syncthreads();
        if (act) {
            #pragma unroll
            for (int kk = 0; kk < BK; ++kk) {
                float ar[TM], bb[TN];
                #pragma unroll
                for (int i = 0; i < TM; ++i) ar[i] = As[kk][ty * TM + i];
                #pragma unroll
                for (int j = 0; j < TN; ++j) bb[j] = Bs[kk][tx * TN + j];
                #pragma unroll
                for (int i = 0; i < TM; ++i)
                    #pragma unroll
                    for (int j = 0; j < TN; ++j)
                        acc[i][j] = fmaf(ar[i], bb[j], acc[i][j]);
            }
        }
        __syncthreads();
    }
    if (act) {
        #pragma unroll
        for (int i = 0; i < TM; ++i) {
            float4* crow = reinterpret_cast<float4*>(
                C + (size_t)(row0h + ty * TM + i) * NMAT + col0 + tx * TN);
            crow[0] = make_float4(acc[i][0], acc[i][1], acc[i][2], acc[i][3]);
            crow[1] = make_float4(acc[i][4], acc[i][5], acc[i][6], acc[i][7]);
        }
    }
#else
    // ------------- sm_103a fast path: cg2 warp-specialized pipeline ---------
    const int wid = tid >> 5, lid = tid & 31;

    extern __shared__ char dsm[];
    const uint32_t raw = smem_u32(dsm);
    const uint32_t sb = (raw + 1023u) & ~1023u;
    const uint32_t s_tmemptr = sb;
    const uint32_t s_full  = sb + 8;            // leader's copy is the real one
    const uint32_t s_empty = sb + 40;           // per-CTA, multicast commits
    const uint32_t s_done  = sb + 72;

    if (wid == 0) { TC_ALLOC_CG2(s_tmemptr, 128); TC_RELINQ_CG2(); }
    if (tid == 0) {
        #pragma unroll
        for (int s = 0; s < STAGES; ++s) {
            MBAR_INIT(s_full + 8 * s, 16);      // 8 warps x 2 CTAs
            MBAR_INIT(s_empty + 8 * s, 1);
        }
        MBAR_INIT(s_done, 1);
    }
    __syncthreads();
    CLUSTER_SYNC();                             // barriers visible cluster-wide
    uint32_t tmem;
    asm volatile("ld.shared.b32 %0, [%1];" : "=r"(tmem) : "r"(s_tmemptr));

    // idesc kind::f16 cg2: dtype=F32, a/btype=BF16, N=128, M=256
    const uint32_t idesc = (1u << 4) | (1u << 7) | (1u << 10)
                         | ((BN / 8) << 17) | ((BM / 16) << 24);

    const int arow0 = row0 + rank * 128;        // this CTA's A rows
    const int bcol0 = col0 + rank * 64;         // this CTA's B cols

    if (tid < PROD) {
        // ---------------- producers: warps 0-7 (both CTAs) ----------------
        for (int i = 0; i < nch; ++i) {
            const int s = i & 3;
            if (i >= 2) {
                CP_WAIT1();
                FENCE_ASYNC();
                __syncwarp();
                if (lid == 0) MBAR_ARRIVE_RANK0(s_full + 8 * ((i - 2) & 3));
            }
            if (i >= 4)
                MBAR_WAIT_PARITY(s_empty + 8 * s, ((i - 4) >> 2) & 1);
            issue_chunk(sb + 1024 + s * STAGE_SZ, arow0, bcol0,
                        row0 + i * KC, tid);
            CP_COMMIT();
        }
        CP_WAIT1();
        FENCE_ASYNC();
        __syncwarp();
        if (lid == 0) MBAR_ARRIVE_RANK0(s_full + 8 * ((nch - 2) & 3));
        CP_WAIT0();
        FENCE_ASYNC();
        __syncwarp();
        if (lid == 0) MBAR_ARRIVE_RANK0(s_full + 8 * ((nch - 1) & 3));
    } else if (rank == 0) {
        // ---------------- MMA warp: warp 8, leader CTA only ----------------
        for (int i = 0; i < nch; ++i) {
            const int s = i & 3;
            MBAR_WAIT_PARITY_CL(s_full + 8 * s, (i >> 2) & 1);
            if (lid == 0) {
                const uint32_t bb = sb + 1024 + s * STAGE_SZ;
                const uint64_t dA0 = mk_desc64(bb + OFF_A0);
                const uint64_t dA1 = mk_desc64(bb + OFF_A1);
                const uint64_t dB0 = mk_desc64(bb + OFF_B0);
                const uint64_t dB1 = mk_desc64(bb + OFF_B1);
                #pragma unroll
                for (int st = 0; st < 2; ++st) {
                    mma_f16_ss_cg2(tmem, dA0 + 2 * st, dB0 + 2 * st, idesc,
                                   (i > 0 || st > 0) ? 1u : 0u);
                    mma_f16_ss_cg2(tmem, dA0 + 2 * st, dB1 + 2 * st, idesc, 1u);
                    mma_f16_ss_cg2(tmem, dA1 + 2 * st, dB0 + 2 * st, idesc, 1u);
                }
                TC_COMMIT_MC2(s_empty + 8 * s, 0x3);   // both CTAs' empty[s]
            }
            __syncwarp();
        }
        if (lid == 0) TC_COMMIT_MC2(s_done, 0x3);
        __syncwarp();
    }

    __syncthreads();
    MBAR_WAIT_PARITY(s_done, 0);
    TC_FENCE_AFTER();

    // epilogue: warps 0-7; this CTA's TMEM holds its 128 rows x 128 cols.
    // warp w: rows (w&3)*32+lid, col half (w>>2)*64 (2 batches of 32).
    if (wid < 8) {
        const int wsub = wid & 3, half = wid >> 2;
        const int r = row0 + rank * 128 + wsub * 32 + lid;
        #pragma unroll
        for (int batch = 0; batch < 2; ++batch) {
            uint32_t rg[32];
            LDTM_X32(rg, tmem + half * 64 + batch * 32);
            TC_WAIT_LD();
            float4* dst = reinterpret_cast<float4*>(
                C + (size_t)r * NMAT + col0 + half * 64 + batch * 32);
            #pragma unroll
            for (int q = 0; q < 8; ++q)
                dst[q] = make_float4(__uint_as_float(rg[4 * q + 0]),
                                     __uint_as_float(rg[4 * q + 1]),
                                     __uint_as_float(rg[4 * q + 2]),
                                     __uint_as_float(rg[4 * q + 3]));
        }
        TC_FENCE_BEFORE();
    }
    __syncthreads();
    if (wid == 0) { TC_DEALLOC_CG2(tmem, 128); }
    CLUSTER_SYNC();                             // no early exit vs peer TMEM ops
#endif
}

// ---------------------------------------------------------------- launch
extern "C" void kernel_launch(void* const* d_in, const int* in_sizes, int n_in,
                              void* d_out, int out_size) {
    const float* A = (const float*)d_in[0];
    const float* B = (const float*)d_in[1];
    float* C = (float*)d_out;

    cudaFuncSetAttribute(trimm_tc_kernel,
                         cudaFuncAttributeMaxDynamicSharedMemorySize, SMEM_NEED);

    split_ab_kernel<<<dim3(NMAT / 64, NMAT / 64, 2), 256>>>(A, B);

    cudaLaunchConfig_t cfg = {};
    cfg.gridDim = dim3(2 * ENTRIES, 1, 1);
    cfg.blockDim = dim3(THREADS, 1, 1);
    cfg.dynamicSmemBytes = SMEM_NEED;
    cudaLaunchAttribute attrs[1];
    attrs[0].id = cudaLaunchAttributeClusterDimension;
    attrs[0].val.clusterDim.x = 2;
    attrs[0].val.clusterDim.y = 1;
    attrs[0].val.clusterDim.z = 1;
    cfg.attrs = attrs;
    cfg.numAttrs = 1;
    cudaLaunchKernelEx(&cfg, trimm_tc_kernel, A, B, C);
}

// round 17
// speedup vs baseline: 1.2792x; 1.2792x over previous
#include <cuda_runtime.h>
#include <cuda_bf16.h>
#include <cstdint>

// C = triu(triu(A) @ triu(B)), N = 4096, fp32.
// sm_103a path: A,B pre-split into masked bf16 hi/lo (B transposed K-major);
// main kernel: warp-specialized pipeline — 8 producer warps (cp.async) +
// 1 MMA warp, per-stage full/empty mbarriers, NO syncthreads in the loop.
// 4 stages, KC=32 (SW64 64B rows), 3 bf16 MMAs per K16 (h*h + h*l + l*h),
// fp32 accum in TMEM, 128x256 tiles, longest-k-first 1D tile schedule.
// Fallback (arch-generic PTX): SIMT fp32 kernel with the same mapping.

constexpr int NMAT = 4096;
constexpr int BM = 128;
constexpr int BN = 256;
constexpr int KC = 32;         // k-chunk (32 bf16 = 64B rows, SW64 native)
constexpr int THREADS = 288;   // 8 producer warps (256) + 1 MMA warp
constexpr int PROD = 256;
constexpr int STAGES = 4;
constexpr int NTILES = 512;    // 32 x 16
constexpr int NCOMPUTE = 272;  // tiles with row0 <= col0+BN-1

// Scratch: masked splits. gA0/gA1: A [r][k]. gB0/gB1: B^T [c][k]. All K-major.
__device__ __align__(1024) __nv_bfloat16 gA0[(size_t)NMAT * NMAT];
__device__ __align__(1024) __nv_bfloat16 gA1[(size_t)NMAT * NMAT];
__device__ __align__(1024) __nv_bfloat16 gB0[(size_t)NMAT * NMAT];
__device__ __align__(1024) __nv_bfloat16 gB1[(size_t)NMAT * NMAT];

// ---------------------------------------------------------------- helpers
__device__ __forceinline__ uint32_t smem_u32(const void* p) {
    uint32_t a;
    asm("{ .reg .u64 t; cvta.to.shared.u64 t, %1; cvt.u32.u64 %0, t; }"
        : "=r"(a) : "l"(p));
    return a;
}

#if defined(__CUDA_ARCH_FEAT_SM103_ALL) || !defined(__CUDA_ARCH__)
__device__ __forceinline__ void mma_f16_ss(uint32_t d, uint64_t ad, uint64_t bd,
                                           uint32_t idesc, uint32_t en) {
    asm volatile(
        "{\n\t.reg .pred p;\n\tsetp.ne.u32 p, %5, 0;\n\t"
        "tcgen05.mma.cta_group::1.kind::f16 [%0], %1, %2, %3, {%4,%4,%4,%4}, p;\n\t}"
        :: "r"(d), "l"(ad), "l"(bd), "r"(idesc), "r"(0u), "r"(en) : "memory");
}
__device__ __forceinline__ void cp_async16(uint32_t dst, const void* src) {
    asm volatile("cp.async.cg.shared.global [%0], [%1], 16;"
                 :: "r"(dst), "l"(src) : "memory");
}
#define CP_COMMIT()      asm volatile("cp.async.commit_group;" ::: "memory")
#define CP_WAIT0()       asm volatile("cp.async.wait_group 0;" ::: "memory")
#define CP_WAIT1()       asm volatile("cp.async.wait_group 1;" ::: "memory")
#define CP_WAIT2()       asm volatile("cp.async.wait_group 2;" ::: "memory")
#define TC_ALLOC(sl, n)  asm volatile("tcgen05.alloc.cta_group::1.sync.aligned.shared::cta.b32 [%0], %1;" :: "r"(sl), "r"((uint32_t)(n)) : "memory")
#define TC_RELINQ()      asm volatile("tcgen05.relinquish_alloc_permit.cta_group::1.sync.aligned;")
#define TC_DEALLOC(t, n) asm volatile("tcgen05.dealloc.cta_group::1.sync.aligned.b32 %0, %1;" :: "r"(t), "r"((uint32_t)(n)))
#define TC_COMMIT(mb)    asm volatile("tcgen05.commit.cta_group::1.mbarrier::arrive::one.shared::cluster.b64 [%0];" :: "r"(mb) : "memory")
#define TC_FENCE_AFTER() asm volatile("tcgen05.fence::after_thread_sync;" ::: "memory")
#define TC_FENCE_BEFORE() asm volatile("tcgen05.fence::before_thread_sync;" ::: "memory")
#define TC_WAIT_LD()     asm volatile("tcgen05.wait::ld.sync.aligned;" ::: "memory")
#define FENCE_ASYNC()    asm volatile("fence.proxy.async.shared::cta;" ::: "memory")
#define MBAR_INIT(mb, c) asm volatile("mbarrier.init.shared.b64 [%0], %1;" :: "r"(mb), "r"((uint32_t)(c)) : "memory")
#define MBAR_ARRIVE(mb)  asm volatile("mbarrier.arrive.shared.b64 _, [%0];" :: "r"(mb) : "memory")

#define MBAR_WAIT_PARITY(mb, ph) do {                                           \
    uint32_t _m = (mb), _p = (ph), _d;                                          \
    asm volatile("{\n\t.reg .pred p;\n\t"                                       \
        "mbarrier.try_wait.parity.acquire.cta.shared::cta.b64 p, [%1], %2;\n\t" \
        "selp.b32 %0, 1, 0, p;\n\t}" : "=r"(_d) : "r"(_m), "r"(_p) : "memory"); \
    if (!_d) {                                                                  \
        asm volatile("{\n\t.reg .pred P1;\n\t"                                  \
        "WL_%=:\n\t"                                                            \
        "mbarrier.try_wait.parity.acquire.cta.shared::cta.b64 P1, [%0], %1, 0x989680;\n\t" \
        "@P1 bra.uni WD_%=;\n\t"                                                \
        "bra.uni WL_%=;\n\t"                                                    \
        "WD_%=:\n\t}" :: "r"(_m), "r"(_p) : "memory");                          \
    }                                                                           \
} while (0)

#define LDTM_X32(r, a)                                                          \
    asm volatile("tcgen05.ld.sync.aligned.32x32b.x32.b32 "                      \
        "{%0, %1, %2, %3, %4, %5, %6, %7, %8, %9, %10, %11, %12, %13, %14, %15,"\
        " %16, %17, %18, %19, %20, %21, %22, %23, %24, %25, %26, %27, %28, %29, %30, %31}, [%32];" \
        : "=r"((r)[0]), "=r"((r)[1]), "=r"((r)[2]), "=r"((r)[3]),               \
          "=r"((r)[4]), "=r"((r)[5]), "=r"((r)[6]), "=r"((r)[7]),               \
          "=r"((r)[8]), "=r"((r)[9]), "=r"((r)[10]), "=r"((r)[11]),             \
          "=r"((r)[12]), "=r"((r)[13]), "=r"((r)[14]), "=r"((r)[15]),           \
          "=r"((r)[16]), "=r"((r)[17]), "=r"((r)[18]), "=r"((r)[19]),           \
          "=r"((r)[20]), "=r"((r)[21]), "=r"((r)[22]), "=r"((r)[23]),           \
          "=r"((r)[24]), "=r"((r)[25]), "=r"((r)[26]), "=r"((r)[27]),           \
          "=r"((r)[28]), "=r"((r)[29]), "=r"((r)[30]), "=r"((r)[31])            \
        : "r"(a))
#endif  // tcgen05 helpers

// SW64 smem descriptor (K-major, 64B rows): layout=SW64(4), ver=1, SBO=32, LBO=1
constexpr uint64_t DESC_BASE_SW64 =
    (uint64_t(4) << 61) | (uint64_t(1) << 46) | (uint64_t(32) << 32) | (uint64_t(1) << 16);
__device__ __forceinline__ uint64_t mk_desc64(uint32_t a) {
    return DESC_BASE_SW64 | ((uint64_t)(a >> 4) & 0x3FFF);
}

__device__ __forceinline__ uint32_t pack_bf16x2(float a, float b) {
    __nv_bfloat162 h = __halves2bfloat162(__float2bfloat16(a), __float2bfloat16(b));
    return *reinterpret_cast<uint32_t*>(&h);
}

// ---------------------------------------------------------------- pre-pass
// z=0: gA0/gA1[r][k] = hi/lo bf16 of (k>=r ? A[r][k] : 0)   (row-major copy)
// z=1: gB0/gB1[c][k] = hi/lo bf16 of (k<=c ? B[k][c] : 0)   (transpose)
// Regions never read by the main kernel are skipped entirely.
__global__ __launch_bounds__(256)
void split_ab_kernel(const float* __restrict__ A, const float* __restrict__ B) {
    const int tid = threadIdx.x;

    if (blockIdx.z == 0) {
        const int rb = blockIdx.y * 64, kb = blockIdx.x * 64;
        if (kb < (rb & ~127)) return;            // k < row0 of main tile: unread
        const int r = rb + (tid >> 2);
        const int k0 = kb + (tid & 3) * 16;
        uint32_t hw[8], lw[8];
        if (kb + 63 < rb) {                       // read, but fully masked
            #pragma unroll
            for (int i = 0; i < 8; ++i) { hw[i] = 0u; lw[i] = 0u; }
        } else {
            #pragma unroll
            for (int q = 0; q < 4; ++q) {
                float4 v = *reinterpret_cast<const float4*>(
                    A + (size_t)r * NMAT + k0 + q * 4);
                const int kg = k0 + q * 4;
                float x0 = (kg + 0 >= r) ? v.x : 0.f;
                float x1 = (kg + 1 >= r) ? v.y : 0.f;
                float x2 = (kg + 2 >= r) ? v.z : 0.f;
                float x3 = (kg + 3 >= r) ? v.w : 0.f;
                float h0 = __bfloat162float(__float2bfloat16(x0));
                float h1 = __bfloat162float(__float2bfloat16(x1));
                float h2 = __bfloat162float(__float2bfloat16(x2));
                float h3 = __bfloat162float(__float2bfloat16(x3));
                hw[2 * q + 0] = pack_bf16x2(x0, x1);
                hw[2 * q + 1] = pack_bf16x2(x2, x3);
                lw[2 * q + 0] = pack_bf16x2(x0 - h0, x1 - h1);
                lw[2 * q + 1] = pack_bf16x2(x2 - h2, x3 - h3);
            }
        }
        uint4* p0 = reinterpret_cast<uint4*>(gA0 + (size_t)r * NMAT + k0);
        uint4* p1 = reinterpret_cast<uint4*>(gA1 + (size_t)r * NMAT + k0);
        p0[0] = make_uint4(hw[0], hw[1], hw[2], hw[3]);
        p0[1] = make_uint4(hw[4], hw[5], hw[6], hw[7]);
        p1[0] = make_uint4(lw[0], lw[1], lw[2], lw[3]);
        p1[1] = make_uint4(lw[4], lw[5], lw[6], lw[7]);
        return;
    }

    // ---- B branch: transpose + mask + split, 64x64 tile staged in smem ----
    const int kb = blockIdx.y * 64, cb = blockIdx.x * 64;
    if (kb >= (cb & ~255) + 256) return;          // k > col0+255: unread
    if (kb > cb + 63) {                           // read, but fully masked
        const uint4 z = make_uint4(0, 0, 0, 0);
        int u = tid * 2;
        int c = u >> 3, s = u & 7;
        uint4* p0 = reinterpret_cast<uint4*>(gB0 + (size_t)(cb + c) * NMAT + kb + s * 8);
        uint4* p1 = reinterpret_cast<uint4*>(gB1 + (size_t)(cb + c) * NMAT + kb + s * 8);
        p0[0] = z; p0[1] = z;
        p1[0] = z; p1[1] = z;
        return;
    }

    __shared__ float s[64][65];
    #pragma unroll
    for (int i = 0; i < 4; ++i) {
        int idx = tid + i * 256;
        int k = idx >> 4, cq = (idx & 15) * 4;
        float4 v = *reinterpret_cast<const float4*>(B + (size_t)(kb + k) * NMAT + cb + cq);
        int kg = kb + k;
        s[k][cq + 0] = (kg <= cb + cq + 0) ? v.x : 0.f;
        s[k][cq + 1] = (kg <= cb + cq + 1) ? v.y : 0.f;
        s[k][cq + 2] = (kg <= cb + cq + 2) ? v.z : 0.f;
        s[k][cq + 3] = (kg <= cb + cq + 3) ? v.w : 0.f;
    }
    __syncthreads();

    const int c = tid >> 2;
    const int ks = (tid & 3) * 16;
    float f[16];
    #pragma unroll
    for (int j = 0; j < 16; ++j) f[j] = s[ks + j][c];
    uint32_t h[8], l[8];
    #pragma unroll
    for (int j = 0; j < 8; ++j) {
        float x0 = f[2 * j], x1 = f[2 * j + 1];
        float h0 = __bfloat162float(__float2bfloat16(x0));
        float h1 = __bfloat162float(__float2bfloat16(x1));
        h[j] = pack_bf16x2(x0, x1);
        l[j] = pack_bf16x2(x0 - h0, x1 - h1);
    }
    uint4* p0 = reinterpret_cast<uint4*>(gB0 + (size_t)(cb + c) * NMAT + kb + ks);
    uint4* p1 = reinterpret_cast<uint4*>(gB1 + (size_t)(cb + c) * NMAT + kb + ks);
    p0[0] = make_uint4(h[0], h[1], h[2], h[3]);
    p0[1] = make_uint4(h[4], h[5], h[6], h[7]);
    p1[0] = make_uint4(l[0], l[1], l[2], l[3]);
    p1[1] = make_uint4(l[4], l[5], l[6], l[7]);
}

// ---------------------------------------------------------------- main GEMM
// smem: ctrl @ +0 (tmemptr @0, full[s] @8+8s, empty[s] @40+8s, done @72);
// STAGES x 48KB buffers @ +1024.
// Per stage: A0 @0 (128x64B=8KB), A1 @8192, B0 @16384 (16KB), B1 @32768.
constexpr int OFF_A0 = 0;
constexpr int OFF_A1 = 8192;
constexpr int OFF_B0 = 16384;
constexpr int OFF_B1 = 32768;
constexpr int STAGE_SZ = 49152;
constexpr int SMEM_NEED = 1024 + STAGES * STAGE_SZ + 1024;

#if defined(__CUDA_ARCH_FEAT_SM103_ALL) || !defined(__CUDA_ARCH__)
__device__ __forceinline__ void issue_chunk(uint32_t bb, int row0, int col0,
                                            int kt, int tid) {
    #pragma unroll
    for (int j = 0; j < 2; ++j) {
        int idx = tid + j * PROD;              // A: 512 segs each
        int m = idx >> 2, seg = idx & 3;
        uint32_t off = m * 64 + seg * 16;
        off ^= (off >> 3) & 0x30;              // SW64
        const __nv_bfloat16* s0 = gA0 + (size_t)(row0 + m) * NMAT + kt + seg * 8;
        const __nv_bfloat16* s1 = gA1 + (size_t)(row0 + m) * NMAT + kt + seg * 8;
        cp_async16(bb + OFF_A0 + off, s0);
        cp_async16(bb + OFF_A1 + off, s1);
    }
    #pragma unroll
    for (int j = 0; j < 4; ++j) {
        int idx = tid + j * PROD;              // B: 1024 segs each
        int crow = idx >> 2, seg = idx & 3;
        uint32_t off = crow * 64 + seg * 16;
        off ^= (off >> 3) & 0x30;              // SW64
        const __nv_bfloat16* s0 = gB0 + (size_t)(col0 + crow) * NMAT + kt + seg * 8;
        const __nv_bfloat16* s1 = gB1 + (size_t)(col0 + crow) * NMAT + kt + seg * 8;
        cp_async16(bb + OFF_B0 + off, s0);
        cp_async16(bb + OFF_B1 + off, s1);
    }
}
#endif

__global__ __launch_bounds__(THREADS, 1)
void trimm_tc_kernel(const float* __restrict__ A,
                     const float* __restrict__ B,
                     float* __restrict__ C) {
    const int bid = blockIdx.x;
    const int tid = threadIdx.x;

    // ---- longest-k-first schedule decode ----
    int br, bc2;
    bool zero_tile = (bid >= NCOMPUTE);
    if (zero_tile) {
        int z = bid - NCOMPUTE;
        int b2 = 0;
        for (;; ++b2) { int cnt = 30 - 2 * b2; if (z < cnt) break; z -= cnt; }
        bc2 = b2; br = 2 * b2 + 2 + z;
    } else {
        int rem = bid, d = 30;
        for (;; --d) {
            int cnt = (d >= 0) ? (16 - ((d + 1) >> 1)) : 16;
            if (rem < cnt) break;
            rem -= cnt;
        }
        int lo = (d >= 0) ? ((d + 1) >> 1) : 0;
        bc2 = lo + rem; br = 2 * bc2 - d;
    }
    const int row0 = br * BM, col0 = bc2 * BN;

    if (zero_tile) {
        const float4 z4 = make_float4(0.f, 0.f, 0.f, 0.f);
        float4* out = reinterpret_cast<float4*>(C + (size_t)row0 * NMAT + col0);
        for (int idx = tid; idx < BM * BN / 4; idx += THREADS)
            out[(size_t)(idx >> 6) * (NMAT / 4) + (idx & 63)] = z4;
        return;
    }

    const int nch = (col0 + BN - row0) / KC;     // 4..128, divisible by 4

#if defined(__CUDA_ARCH__) && !defined(__CUDA_ARCH_FEAT_SM103_ALL)
    // ---------------- arch-generic fallback: SIMT fp32, two 128-col halves --
    constexpr int BK = 8, TM = 8, TN = 8;
    __shared__ float As[BK][128 + 4];
    __shared__ float Bs[BK][128];

    const bool act = (tid < 256);
    const int ty = tid >> 4, tx = tid & 15;
    const int a_row = tid >> 1, a_k = (tid & 1) * 4;
    const int b_k = (tid >> 5) & 7, b_col = (tid & 31) * 4;
    const int arow_g = row0 + (act ? a_row : 0);

    for (int h = 0; h < 2; ++h) {
        const int col0h = col0 + h * 128;
        if (row0 > col0h + 127) {
            const float4 z4 = make_float4(0.f, 0.f, 0.f, 0.f);
            float4* out = reinterpret_cast<float4*>(C + (size_t)row0 * NMAT + col0h);
            for (int idx = tid; idx < BM * 128 / 4; idx += THREADS)
                out[(size_t)(idx >> 5) * (NMAT / 4) + (idx & 31)] = z4;
            continue;
        }
        float acc[TM][TN];
        #pragma unroll
        for (int i = 0; i < TM; ++i)
            #pragma unroll
            for (int j = 0; j < TN; ++j) acc[i][j] = 0.f;
        const int cg = col0h + b_col;
        __syncthreads();
        for (int kt = row0; kt < col0h + 128; kt += BK) {
            if (act) {
                const float4 av = *reinterpret_cast<const float4*>(
                    A + (size_t)arow_g * NMAT + (kt + a_k));
                const int kg = kt + a_k;
                As[a_k + 0][a_row] = (kg + 0 >= arow_g) ? av.x : 0.f;
                As[a_k + 1][a_row] = (kg + 1 >= arow_g) ? av.y : 0.f;
                As[a_k + 2][a_row] = (kg + 2 >= arow_g) ? av.z : 0.f;
                As[a_k + 3][a_row] = (kg + 3 >= arow_g) ? av.w : 0.f;
                const int bkg = kt + b_k;
                float4 bv = *reinterpret_cast<const float4*>(B + (size_t)bkg * NMAT + cg);
                bv.x = (bkg <= cg + 0) ? bv.x : 0.f;
                bv.y = (bkg <= cg + 1) ? bv.y : 0.f;
                bv.z = (bkg <= cg + 2) ? bv.z : 0.f;
                bv.w = (bkg <= cg + 3) ? bv.w : 0.f;
                *reinterpret_cast<float4*>(&Bs[b_k][b_col]) = bv;
            }
            __syncthreads();
            if (act) {
                #pragma unroll
                for (int kk = 0; kk < BK; ++kk) {
                    float ar[TM], bb[TN];
                    #pragma unroll
                    for (int i = 0; i < TM; ++i) ar[i] = As[kk][ty * TM + i];
                    #pragma unroll
                    for (int j = 0; j < TN; ++j) bb[j] = Bs[kk][tx * TN + j];
                    #pragma unroll
                    for (int i = 0; i < TM; ++i)
                        #pragma unroll
                        for (int j = 0; j < TN; ++j)
                            acc[i][j] = fmaf(ar[i], bb[j], acc[i][j]);
                }
            }
            __syncthreads();
        }
        if (act) {
            #pragma unroll
            for (int i = 0; i < TM; ++i) {
                float4* crow = reinterpret_cast<float4*>(
                    C + (size_t)(row0 + ty * TM + i) * NMAT + col0h + tx * TN);
                crow[0] = make_float4(acc[i][0], acc[i][1], acc[i][2], acc[i][3]);
                crow[1] = make_float4(acc[i][4], acc[i][5], acc[i][6], acc[i][7]);
            }
        }
    }
#else
    // ------------- sm_103a fast path: warp-specialized cp.async -> tcgen05 --
    const int wid = tid >> 5, lid = tid & 31;

    extern __shared__ char dsm[];
    const uint32_t raw = smem_u32(dsm);
    const uint32_t sb = (raw + 1023u) & ~1023u;
    const uint32_t s_tmemptr = sb;
    const uint32_t s_full  = sb + 8;
    const uint32_t s_empty = sb + 40;
    const uint32_t s_done  = sb + 72;

    if (wid == 0) { TC_ALLOC(s_tmemptr, 256); TC_RELINQ(); }
    if (tid == 0) {
        #pragma unroll
        for (int s = 0; s < STAGES; ++s) {
            MBAR_INIT(s_full + 8 * s, PROD);    // 256 producer arrivals
            MBAR_INIT(s_empty + 8 * s, 1);      // tcgen05.commit arrival
        }
        MBAR_INIT(s_done, 1);
    }
    __syncthreads();
    uint32_t tmem;
    asm volatile("ld.shared.b32 %0, [%1];" : "=r"(tmem) : "r"(s_tmemptr));

    // idesc kind::f16: dtype=F32, a/btype=BF16, N=256, M=128
    const uint32_t idesc = (1u << 4) | (1u << 7) | (1u << 10)
                         | ((BN / 8) << 17) | ((BM / 16) << 24);

    if (tid < PROD) {
        // ---------------- producers: warps 0-7 ----------------
        for (int i = 0; i < nch; ++i) {
            const int s = i & 3;
            if (i >= 4)  // stage s last used by chunk i-4; wait its MMA done
                MBAR_WAIT_PARITY(s_empty + 8 * s, ((i - 4) >> 2) & 1);
            issue_chunk(sb + 1024 + s * STAGE_SZ, row0, col0, row0 + i * KC, tid);
            CP_COMMIT();
            if (i >= 2) {            // group i-2 complete -> signal its stage
                CP_WAIT2();
                MBAR_ARRIVE(s_full + 8 * ((i - 2) & 3));
            }
        }
        CP_WAIT1();
        MBAR_ARRIVE(s_full + 8 * ((nch - 2) & 3));
        CP_WAIT0();
        MBAR_ARRIVE(s_full + 8 * ((nch - 1) & 3));
    } else {
        // ---------------- MMA warp: warp 8 ----------------
        // Hoisted per-stage descriptors (4 sets, computed once).
        uint64_t hA0[STAGES], hA1[STAGES], hB0[STAGES], hB1[STAGES];
        #pragma unroll
        for (int s = 0; s < STAGES; ++s) {
            const uint32_t bb = sb + 1024 + s * STAGE_SZ;
            hA0[s] = mk_desc64(bb + OFF_A0);
            hA1[s] = mk_desc64(bb + OFF_A1);
            hB0[s] = mk_desc64(bb + OFF_B0);
            hB1[s] = mk_desc64(bb + OFF_B1);
        }
        for (int i = 0; i < nch; ++i) {
            const int s = i & 3;
            MBAR_WAIT_PARITY(s_full + 8 * s, (i >> 2) & 1);
            FENCE_ASYNC();
            if (lid == 0) {
                const uint64_t dA0 = hA0[s], dA1 = hA1[s];
                const uint64_t dB0 = hB0[s], dB1 = hB1[s];
                #pragma unroll
                for (int st = 0; st < 2; ++st) {
                    mma_f16_ss(tmem, dA0 + 2 * st, dB0 + 2 * st, idesc,
                               (i > 0 || st > 0) ? 1u : 0u);
                    mma_f16_ss(tmem, dA0 + 2 * st, dB1 + 2 * st, idesc, 1u);
                    mma_f16_ss(tmem, dA1 + 2 * st, dB0 + 2 * st, idesc, 1u);
                }
                TC_COMMIT(s_empty + 8 * s);     // MMA(i) done -> stage free
            }
        }
        if (lid == 0) TC_COMMIT(s_done);        // all MMAs complete
        __syncwarp();
    }

    __syncthreads();
    MBAR_WAIT_PARITY(s_done, 0);
    TC_FENCE_AFTER();

    // epilogue: warps 0-7; warp w covers rows (w&3)*32+lid, half=(w>>2)*128
    if (wid < 8) {
        const int wsub = wid & 3, half = wid >> 2;
        const int r = row0 + wsub * 32 + lid;
        #pragma unroll
        for (int batch = 0; batch < 4; ++batch) {
            uint32_t rg[32];
            LDTM_X32(rg, tmem + half * 128 + batch * 32);
            TC_WAIT_LD();
            float4* dst = reinterpret_cast<float4*>(
                C + (size_t)r * NMAT + col0 + half * 128 + batch * 32);
            #pragma unroll
            for (int q = 0; q < 8; ++q)
                dst[q] = make_float4(__uint_as_float(rg[4 * q + 0]),
                                     __uint_as_float(rg[4 * q + 1]),
                                     __uint_as_float(rg[4 * q + 2]),
                                     __uint_as_float(rg[4 * q + 3]));
        }
        TC_FENCE_BEFORE();
    }
    __syncthreads();
    if (wid == 0) { TC_DEALLOC(tmem, 256); }
#endif
}

// ---------------------------------------------------------------- launch
extern "C" void kernel_launch(void* const* d_in, const int* in_sizes, int n_in,
                              void* d_out, int out_size) {
    const float* A = (const float*)d_in[0];
    const float* B = (const float*)d_in[1];
    float* C = (float*)d_out;

    cudaFuncSetAttribute(trimm_tc_kernel,
                         cudaFuncAttributeMaxDynamicSharedMemorySize, SMEM_NEED);

    split_ab_kernel<<<dim3(NMAT / 64, NMAT / 64, 2), 256>>>(A, B);
    trimm_tc_kernel<<<NTILES, THREADS, SMEM_NEED>>>(A, B, C);
}